// round 3
// baseline (speedup 1.0000x reference)
#include <cuda_runtime.h>
#include <cuda_bf16.h>
#include <math_constants.h>

// Fixed problem shapes
#define B_ 2
#define T_ 2048
#define D_ 1024
#define H_ 16
#define HD_ 64
#define NTOK (B_ * T_)          // 4096
#define MQKV (3 * D_)           // 3072

// Scratch (allocation-free rule: __device__ globals)
__device__ float g_qkv[NTOK * MQKV];                       // [4096, 3072]
__device__ float g_S[(size_t)B_ * H_ * T_ * T_];           // [32, 2048, 2048] scores -> probs in place
__device__ float g_ctx[NTOK * D_];                         // [4096, 1024]

// ---------------------------------------------------------------------------
// Generic NT SGEMM: C[N,M] = A[N,K] @ B[M,K]^T   (both row-major, K-contig)
// BM=BN=128, BK=16, 256 threads, 8x8 per thread.
// ---------------------------------------------------------------------------
__global__ __launch_bounds__(256) void sgemm_nt(
    const float* __restrict__ A, const float* __restrict__ Bm,
    float* __restrict__ C, int Mcols, int K)
{
    __shared__ float As[16][128];
    __shared__ float Bs[16][128];

    const int tid = threadIdx.x;
    const int tx = tid & 15;
    const int ty = tid >> 4;
    const int rowBase = blockIdx.y * 128;
    const int colBase = blockIdx.x * 128;

    float acc[8][8];
#pragma unroll
    for (int i = 0; i < 8; i++)
#pragma unroll
        for (int j = 0; j < 8; j++) acc[i][j] = 0.f;

    for (int k0 = 0; k0 < K; k0 += 16) {
#pragma unroll
        for (int l = 0; l < 2; l++) {
            int idx = l * 256 + tid;          // 0..511
            int r   = idx >> 2;               // 0..127
            int c4  = (idx & 3) * 4;          // 0,4,8,12
            float4 av = *(const float4*)(A  + (size_t)(rowBase + r) * K + k0 + c4);
            As[c4 + 0][r] = av.x; As[c4 + 1][r] = av.y;
            As[c4 + 2][r] = av.z; As[c4 + 3][r] = av.w;
            float4 bv = *(const float4*)(Bm + (size_t)(colBase + r) * K + k0 + c4);
            Bs[c4 + 0][r] = bv.x; Bs[c4 + 1][r] = bv.y;
            Bs[c4 + 2][r] = bv.z; Bs[c4 + 3][r] = bv.w;
        }
        __syncthreads();

#pragma unroll
        for (int kk = 0; kk < 16; kk++) {
            float4 a0 = *(const float4*)&As[kk][ty * 8];
            float4 a1 = *(const float4*)&As[kk][ty * 8 + 4];
            float4 b0 = *(const float4*)&Bs[kk][tx * 8];
            float4 b1 = *(const float4*)&Bs[kk][tx * 8 + 4];
            float a[8] = {a0.x, a0.y, a0.z, a0.w, a1.x, a1.y, a1.z, a1.w};
            float b[8] = {b0.x, b0.y, b0.z, b0.w, b1.x, b1.y, b1.z, b1.w};
#pragma unroll
            for (int i = 0; i < 8; i++)
#pragma unroll
                for (int j = 0; j < 8; j++) acc[i][j] = fmaf(a[i], b[j], acc[i][j]);
        }
        __syncthreads();
    }

#pragma unroll
    for (int i = 0; i < 8; i++) {
        float* crow = C + (size_t)(rowBase + ty * 8 + i) * Mcols + colBase + tx * 8;
#pragma unroll
        for (int j = 0; j < 8; j += 4) {
            float4 v = make_float4(acc[i][j], acc[i][j+1], acc[i][j+2], acc[i][j+3]);
            *(float4*)(crow + j) = v;
        }
    }
}

// ---------------------------------------------------------------------------
// Scores: S[bh,i,j] = 0.125 * dot(q_i, k_j) - slope_h * (i - j), j <= i only.
// 64x64 tiles, upper-triangle tiles skipped entirely.
// ---------------------------------------------------------------------------
__global__ __launch_bounds__(256) void scores_kernel(
    const float* __restrict__ qkv, float* __restrict__ S)
{
    const int tj = blockIdx.x;
    const int ti = blockIdx.y;
    if (tj > ti) return;
    const int bh = blockIdx.z;
    const int b  = bh >> 4;
    const int h  = bh & 15;

    __shared__ float Qs[64][65];   // Qs[e][i], padded
    __shared__ float Ks[64][65];   // Ks[e][j], padded

    const int tid = threadIdx.x;
    const float* qbase = qkv + (size_t)(b * T_) * MQKV + h * HD_;

    for (int idx = tid; idx < 64 * 16; idx += 256) {
        int r  = idx >> 4;
        int e4 = (idx & 15) * 4;
        float4 qv = *(const float4*)(qbase + (size_t)(ti * 64 + r) * MQKV + e4);
        Qs[e4 + 0][r] = qv.x; Qs[e4 + 1][r] = qv.y;
        Qs[e4 + 2][r] = qv.z; Qs[e4 + 3][r] = qv.w;
        float4 kv = *(const float4*)(qbase + D_ + (size_t)(tj * 64 + r) * MQKV + e4);
        Ks[e4 + 0][r] = kv.x; Ks[e4 + 1][r] = kv.y;
        Ks[e4 + 2][r] = kv.z; Ks[e4 + 3][r] = kv.w;
    }
    __syncthreads();

    const int tx = tid & 15;
    const int ty = tid >> 4;

    float acc[4][4];
#pragma unroll
    for (int i = 0; i < 4; i++)
#pragma unroll
        for (int j = 0; j < 4; j++) acc[i][j] = 0.f;

#pragma unroll 16
    for (int e = 0; e < 64; e++) {
        float a[4], bb[4];
#pragma unroll
        for (int i = 0; i < 4; i++) a[i]  = Qs[e][ty * 4 + i];
#pragma unroll
        for (int j = 0; j < 4; j++) bb[j] = Ks[e][tx * 4 + j];
#pragma unroll
        for (int i = 0; i < 4; i++)
#pragma unroll
            for (int j = 0; j < 4; j++) acc[i][j] = fmaf(a[i], bb[j], acc[i][j]);
    }

    const float slope = exp2f(-(float)(h + 1) / 16.f);
    const float scale = 0.125f;   // hd^-0.5
    float* Sbh = S + (size_t)bh * T_ * T_;

#pragma unroll
    for (int i = 0; i < 4; i++) {
        int gi = ti * 64 + ty * 4 + i;
#pragma unroll
        for (int j = 0; j < 4; j++) {
            int gj = tj * 64 + tx * 4 + j;
            if (gj <= gi)
                Sbh[(size_t)gi * T_ + gj] = acc[i][j] * scale - slope * (float)(gi - gj);
        }
    }
}

// ---------------------------------------------------------------------------
// Row softmax over j in [0, i]; zero-pad up to next 64 boundary so PV GEMM
// needs no masking. One block per (row, bh).
// ---------------------------------------------------------------------------
__global__ __launch_bounds__(128) void softmax_kernel(float* __restrict__ S)
{
    const int i  = blockIdx.x;
    const int bh = blockIdx.y;
    float* row = S + ((size_t)bh * T_ + i) * T_;
    const int n = i + 1;
    const int tid = threadIdx.x;
    __shared__ float red[4];

    float m = -CUDART_INF_F;
    for (int j = tid; j < n; j += 128) m = fmaxf(m, row[j]);
#pragma unroll
    for (int o = 16; o; o >>= 1) m = fmaxf(m, __shfl_xor_sync(0xffffffffu, m, o));
    if ((tid & 31) == 0) red[tid >> 5] = m;
    __syncthreads();
    m = fmaxf(fmaxf(red[0], red[1]), fmaxf(red[2], red[3]));
    __syncthreads();

    float s = 0.f;
    for (int j = tid; j < n; j += 128) {
        float e = __expf(row[j] - m);
        row[j] = e;
        s += e;
    }
#pragma unroll
    for (int o = 16; o; o >>= 1) s += __shfl_xor_sync(0xffffffffu, s, o);
    if ((tid & 31) == 0) red[tid >> 5] = s;
    __syncthreads();
    s = red[0] + red[1] + red[2] + red[3];

    const float inv = 1.f / s;
    const int npad = (n + 63) & ~63;
    for (int j = tid; j < npad; j += 128) row[j] = (j < n) ? row[j] * inv : 0.f;
}

// ---------------------------------------------------------------------------
// ctx[b, i, h*64+e] = sum_{j<=i} P[bh,i,j] * V[bh,j,e]
// One block per (i-tile, bh); loops only causal j-tiles.
// ---------------------------------------------------------------------------
__global__ __launch_bounds__(256) void av_kernel(
    const float* __restrict__ S, const float* __restrict__ qkv,
    float* __restrict__ ctx)
{
    const int ti = blockIdx.x;
    const int bh = blockIdx.y;
    const int b  = bh >> 4;
    const int h  = bh & 15;

    __shared__ float Ps[64][65];   // Ps[j][i], padded
    __shared__ float Vs[64][64];   // Vs[j][e]

    const int tid = threadIdx.x;
    const int tx = tid & 15;
    const int ty = tid >> 4;

    float acc[4][4];
#pragma unroll
    for (int i = 0; i < 4; i++)
#pragma unroll
        for (int j = 0; j < 4; j++) acc[i][j] = 0.f;

    const float* Pbase = S + (size_t)bh * T_ * T_;
    const float* vbase = qkv + (size_t)(b * T_) * MQKV + 2 * D_ + h * HD_;

    for (int jt = 0; jt <= ti; jt++) {
        for (int idx = tid; idx < 64 * 16; idx += 256) {
            int r  = idx >> 4;
            int c4 = (idx & 15) * 4;
            float4 pv = *(const float4*)(Pbase + (size_t)(ti * 64 + r) * T_ + jt * 64 + c4);
            Ps[c4 + 0][r] = pv.x; Ps[c4 + 1][r] = pv.y;
            Ps[c4 + 2][r] = pv.z; Ps[c4 + 3][r] = pv.w;
            float4 vv = *(const float4*)(vbase + (size_t)(jt * 64 + r) * MQKV + c4);
            *(float4*)&Vs[r][c4] = vv;
        }
        __syncthreads();

#pragma unroll 16
        for (int j = 0; j < 64; j++) {
            float a[4], bb[4];
#pragma unroll
            for (int i = 0; i < 4; i++) a[i]  = Ps[j][ty * 4 + i];
#pragma unroll
            for (int e = 0; e < 4; e++) bb[e] = Vs[j][tx * 4 + e];
#pragma unroll
            for (int i = 0; i < 4; i++)
#pragma unroll
                for (int e = 0; e < 4; e++) acc[i][e] = fmaf(a[i], bb[e], acc[i][e]);
        }
        __syncthreads();
    }

#pragma unroll
    for (int i = 0; i < 4; i++) {
        int gi = ti * 64 + ty * 4 + i;                  // token within this b
        float* crow = ctx + (size_t)(b * T_ + gi) * D_ + h * HD_ + tx * 4;
        float4 v = make_float4(acc[i][0], acc[i][1], acc[i][2], acc[i][3]);
        *(float4*)crow = v;
    }
}

// ---------------------------------------------------------------------------
extern "C" void kernel_launch(void* const* d_in, const int* in_sizes, int n_in,
                              void* d_out, int out_size)
{
    const float* x     = (const float*)d_in[0];
    const float* w_qkv = (const float*)d_in[1];
    const float* w_out = (const float*)d_in[2];
    float* out = (float*)d_out;

    float *qkv_p, *S_p, *ctx_p;
    cudaGetSymbolAddress((void**)&qkv_p, g_qkv);
    cudaGetSymbolAddress((void**)&S_p,   g_S);
    cudaGetSymbolAddress((void**)&ctx_p, g_ctx);

    // 1) QKV projection: [4096,1024] @ [3072,1024]^T -> [4096,3072]
    sgemm_nt<<<dim3(MQKV / 128, NTOK / 128), 256>>>(x, w_qkv, qkv_p, MQKV, D_);

    // 2) Scores (causal tiles only) + scale + ALiBi
    scores_kernel<<<dim3(T_ / 64, T_ / 64, B_ * H_), 256>>>(qkv_p, S_p);

    // 3) Row softmax (in place) with zero-padding of the diagonal tile
    softmax_kernel<<<dim3(T_, B_ * H_), 128>>>(S_p);

    // 4) P @ V -> ctx in [B,T,D] layout
    av_kernel<<<dim3(T_ / 64, B_ * H_), 256>>>(S_p, qkv_p, ctx_p);

    // 5) Output projection: [4096,1024] @ [1024,1024]^T -> out
    sgemm_nt<<<dim3(D_ / 128, NTOK / 128), 256>>>(ctx_p, w_out, out, D_, D_);
}

// round 6
// speedup vs baseline: 1.3835x; 1.3835x over previous
#include <cuda_runtime.h>
#include <cuda_bf16.h>
#include <math_constants.h>

// Fixed problem shapes
#define B_ 2
#define T_ 2048
#define D_ 1024
#define H_ 16
#define HD_ 64
#define NTOK (B_ * T_)          // 4096
#define MQKV (3 * D_)           // 3072
#define K_ 1024

// Scratch (allocation-free rule: __device__ globals)
__device__ float g_qkv[NTOK * MQKV];                       // [4096, 3072]
__device__ float g_S[(size_t)B_ * H_ * T_ * T_];           // [32, 2048, 2048]
__device__ float g_ctx[NTOK * D_];                         // [4096, 1024]

// bf16 hi/lo split scratch
__device__ __nv_bfloat16 g_xhi[NTOK * K_],  g_xlo[NTOK * K_];
__device__ __nv_bfloat16 g_wqhi[MQKV * K_], g_wqlo[MQKV * K_];
__device__ __nv_bfloat16 g_wohi[D_ * K_],   g_wolo[D_ * K_];
__device__ __nv_bfloat16 g_chi[NTOK * K_],  g_clo[NTOK * K_];

// ---------------------------------------------------------------------------
// Split fp32 -> bf16 hi + bf16 lo (residual). Vectorized by 4.
// ---------------------------------------------------------------------------
__global__ __launch_bounds__(256) void split_bf16(
    const float* __restrict__ in, __nv_bfloat16* __restrict__ hi,
    __nv_bfloat16* __restrict__ lo, int n4)
{
    int i = blockIdx.x * 256 + threadIdx.x;
    if (i >= n4) return;
    float4 v = ((const float4*)in)[i];
    __nv_bfloat16 h0 = __float2bfloat16(v.x);
    __nv_bfloat16 h1 = __float2bfloat16(v.y);
    __nv_bfloat16 h2 = __float2bfloat16(v.z);
    __nv_bfloat16 h3 = __float2bfloat16(v.w);
    __nv_bfloat162 hp0 = __nv_bfloat162(h0, h1);
    __nv_bfloat162 hp1 = __nv_bfloat162(h2, h3);
    __nv_bfloat162 lp0 = __nv_bfloat162(__float2bfloat16(v.x - __bfloat162float(h0)),
                                        __float2bfloat16(v.y - __bfloat162float(h1)));
    __nv_bfloat162 lp1 = __nv_bfloat162(__float2bfloat16(v.z - __bfloat162float(h2)),
                                        __float2bfloat16(v.w - __bfloat162float(h3)));
    ((__nv_bfloat162*)hi)[i * 2 + 0] = hp0;
    ((__nv_bfloat162*)hi)[i * 2 + 1] = hp1;
    ((__nv_bfloat162*)lo)[i * 2 + 0] = lp0;
    ((__nv_bfloat162*)lo)[i * 2 + 1] = lp1;
}

// ---------------------------------------------------------------------------
// Tensor-core NT GEMM, bf16x3 split: C[N,M] = A[N,K] @ W[M,K]^T in ~fp32 prec.
// mma.sync.m16n8k16.bf16. Block 128x128, BK=32, 8 warps, warp tile 64x32.
// ---------------------------------------------------------------------------
#define BM 128
#define BN 128
#define BK 32
#define SSTR 40   // smem row stride in bf16 (80B -> conflict-free frag loads)

__device__ __forceinline__ void mma16816(float c[4], const unsigned a[4], const unsigned b[2])
{
    asm volatile(
        "mma.sync.aligned.m16n8k16.row.col.f32.bf16.bf16.f32 "
        "{%0,%1,%2,%3}, {%4,%5,%6,%7}, {%8,%9}, {%0,%1,%2,%3};\n"
        : "+f"(c[0]), "+f"(c[1]), "+f"(c[2]), "+f"(c[3])
        : "r"(a[0]), "r"(a[1]), "r"(a[2]), "r"(a[3]), "r"(b[0]), "r"(b[1]));
}

__global__ __launch_bounds__(256) void gemm_bf16x3(
    const __nv_bfloat16* __restrict__ Ahi, const __nv_bfloat16* __restrict__ Alo,
    const __nv_bfloat16* __restrict__ Whi, const __nv_bfloat16* __restrict__ Wlo,
    float* __restrict__ C, int Mcols)
{
    __shared__ __nv_bfloat16 sAhi[BM][SSTR], sAlo[BM][SSTR];
    __shared__ __nv_bfloat16 sBhi[BN][SSTR], sBlo[BN][SSTR];

    const int tid  = threadIdx.x;
    const int warp = tid >> 5;
    const int lane = tid & 31;
    const int wm = warp >> 2;          // 0..1
    const int wn = warp & 3;           // 0..3
    const int g  = lane >> 2;          // 0..7
    const int tg = lane & 3;           // 0..3
    const int rowBase = blockIdx.y * BM;
    const int colBase = blockIdx.x * BN;

    // per-thread global load coords (2 uint4 per matrix)
    const int r0 = tid >> 1;                 // 0..127 (for l via idx)
    (void)r0;

    float acc[4][4][4];
#pragma unroll
    for (int im = 0; im < 4; im++)
#pragma unroll
        for (int in = 0; in < 4; in++)
#pragma unroll
            for (int q = 0; q < 4; q++) acc[im][in][q] = 0.f;

    uint4 pAh[2], pAl[2], pBh[2], pBl[2];

    // prologue: prefetch k0 = 0
#pragma unroll
    for (int l = 0; l < 2; l++) {
        int idx = l * 256 + tid;
        int r = idx >> 2, c8 = (idx & 3) * 8;
        pAh[l] = *(const uint4*)(Ahi + (size_t)(rowBase + r) * K_ + c8);
        pAl[l] = *(const uint4*)(Alo + (size_t)(rowBase + r) * K_ + c8);
        pBh[l] = *(const uint4*)(Whi + (size_t)(colBase + r) * K_ + c8);
        pBl[l] = *(const uint4*)(Wlo + (size_t)(colBase + r) * K_ + c8);
    }

    for (int k0 = 0; k0 < K_; k0 += BK) {
        // regs -> smem
#pragma unroll
        for (int l = 0; l < 2; l++) {
            int idx = l * 256 + tid;
            int r = idx >> 2, c8 = (idx & 3) * 8;
            *(uint4*)&sAhi[r][c8] = pAh[l];
            *(uint4*)&sAlo[r][c8] = pAl[l];
            *(uint4*)&sBhi[r][c8] = pBh[l];
            *(uint4*)&sBlo[r][c8] = pBl[l];
        }
        __syncthreads();

        // prefetch next k-slab into regs
        if (k0 + BK < K_) {
#pragma unroll
            for (int l = 0; l < 2; l++) {
                int idx = l * 256 + tid;
                int r = idx >> 2, c8 = (idx & 3) * 8;
                pAh[l] = *(const uint4*)(Ahi + (size_t)(rowBase + r) * K_ + k0 + BK + c8);
                pAl[l] = *(const uint4*)(Alo + (size_t)(rowBase + r) * K_ + k0 + BK + c8);
                pBh[l] = *(const uint4*)(Whi + (size_t)(colBase + r) * K_ + k0 + BK + c8);
                pBl[l] = *(const uint4*)(Wlo + (size_t)(colBase + r) * K_ + k0 + BK + c8);
            }
        }

#pragma unroll
        for (int ks = 0; ks < BK; ks += 16) {
            unsigned ahi[4][4], alo[4][4], bhi[4][2], blo[4][2];
            const int c0 = ks + tg * 2;
#pragma unroll
            for (int im = 0; im < 4; im++) {
                int ra = wm * 64 + im * 16 + g;
                ahi[im][0] = *(const unsigned*)&sAhi[ra][c0];
                ahi[im][1] = *(const unsigned*)&sAhi[ra + 8][c0];
                ahi[im][2] = *(const unsigned*)&sAhi[ra][c0 + 8];
                ahi[im][3] = *(const unsigned*)&sAhi[ra + 8][c0 + 8];
                alo[im][0] = *(const unsigned*)&sAlo[ra][c0];
                alo[im][1] = *(const unsigned*)&sAlo[ra + 8][c0];
                alo[im][2] = *(const unsigned*)&sAlo[ra][c0 + 8];
                alo[im][3] = *(const unsigned*)&sAlo[ra + 8][c0 + 8];
            }
#pragma unroll
            for (int in = 0; in < 4; in++) {
                int nb = wn * 32 + in * 8 + g;
                bhi[in][0] = *(const unsigned*)&sBhi[nb][c0];
                bhi[in][1] = *(const unsigned*)&sBhi[nb][c0 + 8];
                blo[in][0] = *(const unsigned*)&sBlo[nb][c0];
                blo[in][1] = *(const unsigned*)&sBlo[nb][c0 + 8];
            }
#pragma unroll
            for (int im = 0; im < 4; im++)
#pragma unroll
                for (int in = 0; in < 4; in++) {
                    mma16816(acc[im][in], ahi[im], bhi[in]);
                    mma16816(acc[im][in], ahi[im], blo[in]);
                    mma16816(acc[im][in], alo[im], bhi[in]);
                }
        }
        __syncthreads();
    }

    // epilogue: fragment layout c0,c1 -> (row g, col 2tg..), c2,c3 -> (row g+8)
#pragma unroll
    for (int im = 0; im < 4; im++) {
#pragma unroll
        for (int in = 0; in < 4; in++) {
            int row = rowBase + wm * 64 + im * 16 + g;
            int col = colBase + wn * 32 + in * 8 + tg * 2;
            float2 v01 = make_float2(acc[im][in][0], acc[im][in][1]);
            float2 v23 = make_float2(acc[im][in][2], acc[im][in][3]);
            *(float2*)(C + (size_t)row * Mcols + col)       = v01;
            *(float2*)(C + (size_t)(row + 8) * Mcols + col) = v23;
        }
    }
}

// ---------------------------------------------------------------------------
// Scores: S[bh,i,j] = 0.125 * dot(q_i, k_j) - slope_h * (i - j), j <= i only.
// ---------------------------------------------------------------------------
__global__ __launch_bounds__(256) void scores_kernel(
    const float* __restrict__ qkv, float* __restrict__ S)
{
    const int tj = blockIdx.x;
    const int ti = blockIdx.y;
    if (tj > ti) return;
    const int bh = blockIdx.z;
    const int b  = bh >> 4;
    const int h  = bh & 15;

    __shared__ float Qs[64][65];
    __shared__ float Ks[64][65];

    const int tid = threadIdx.x;
    const float* qbase = qkv + (size_t)(b * T_) * MQKV + h * HD_;

    for (int idx = tid; idx < 64 * 16; idx += 256) {
        int r  = idx >> 4;
        int e4 = (idx & 15) * 4;
        float4 qv = *(const float4*)(qbase + (size_t)(ti * 64 + r) * MQKV + e4);
        Qs[e4 + 0][r] = qv.x; Qs[e4 + 1][r] = qv.y;
        Qs[e4 + 2][r] = qv.z; Qs[e4 + 3][r] = qv.w;
        float4 kv = *(const float4*)(qbase + D_ + (size_t)(tj * 64 + r) * MQKV + e4);
        Ks[e4 + 0][r] = kv.x; Ks[e4 + 1][r] = kv.y;
        Ks[e4 + 2][r] = kv.z; Ks[e4 + 3][r] = kv.w;
    }
    __syncthreads();

    const int tx = tid & 15;
    const int ty = tid >> 4;

    float acc[4][4];
#pragma unroll
    for (int i = 0; i < 4; i++)
#pragma unroll
        for (int j = 0; j < 4; j++) acc[i][j] = 0.f;

#pragma unroll 16
    for (int e = 0; e < 64; e++) {
        float a[4], bb[4];
#pragma unroll
        for (int i = 0; i < 4; i++) a[i]  = Qs[e][ty * 4 + i];
#pragma unroll
        for (int j = 0; j < 4; j++) bb[j] = Ks[e][tx * 4 + j];
#pragma unroll
        for (int i = 0; i < 4; i++)
#pragma unroll
            for (int j = 0; j < 4; j++) acc[i][j] = fmaf(a[i], bb[j], acc[i][j]);
    }

    const float slope = exp2f(-(float)(h + 1) / 16.f);
    const float scale = 0.125f;
    float* Sbh = S + (size_t)bh * T_ * T_;

#pragma unroll
    for (int i = 0; i < 4; i++) {
        int gi = ti * 64 + ty * 4 + i;
#pragma unroll
        for (int j = 0; j < 4; j++) {
            int gj = tj * 64 + tx * 4 + j;
            if (gj <= gi)
                Sbh[(size_t)gi * T_ + gj] = acc[i][j] * scale - slope * (float)(gi - gj);
        }
    }
}

// ---------------------------------------------------------------------------
// Row softmax over j in [0, i]; zero-pad up to next 64 boundary.
// ---------------------------------------------------------------------------
__global__ __launch_bounds__(128) void softmax_kernel(float* __restrict__ S)
{
    const int i  = blockIdx.x;
    const int bh = blockIdx.y;
    float* row = S + ((size_t)bh * T_ + i) * T_;
    const int n = i + 1;
    const int tid = threadIdx.x;
    __shared__ float red[4];

    float m = -CUDART_INF_F;
    for (int j = tid; j < n; j += 128) m = fmaxf(m, row[j]);
#pragma unroll
    for (int o = 16; o; o >>= 1) m = fmaxf(m, __shfl_xor_sync(0xffffffffu, m, o));
    if ((tid & 31) == 0) red[tid >> 5] = m;
    __syncthreads();
    m = fmaxf(fmaxf(red[0], red[1]), fmaxf(red[2], red[3]));
    __syncthreads();

    float s = 0.f;
    for (int j = tid; j < n; j += 128) {
        float e = __expf(row[j] - m);
        row[j] = e;
        s += e;
    }
#pragma unroll
    for (int o = 16; o; o >>= 1) s += __shfl_xor_sync(0xffffffffu, s, o);
    if ((tid & 31) == 0) red[tid >> 5] = s;
    __syncthreads();
    s = red[0] + red[1] + red[2] + red[3];

    const float inv = 1.f / s;
    const int npad = (n + 63) & ~63;
    for (int j = tid; j < npad; j += 128) row[j] = (j < n) ? row[j] * inv : 0.f;
}

// ---------------------------------------------------------------------------
// ctx[b, i, h*64+e] = sum_{j<=i} P[bh,i,j] * V[bh,j,e]
// ---------------------------------------------------------------------------
__global__ __launch_bounds__(256) void av_kernel(
    const float* __restrict__ S, const float* __restrict__ qkv,
    float* __restrict__ ctx)
{
    const int ti = blockIdx.x;
    const int bh = blockIdx.y;
    const int b  = bh >> 4;
    const int h  = bh & 15;

    __shared__ float Ps[64][65];
    __shared__ float Vs[64][64];

    const int tid = threadIdx.x;
    const int tx = tid & 15;
    const int ty = tid >> 4;

    float acc[4][4];
#pragma unroll
    for (int i = 0; i < 4; i++)
#pragma unroll
        for (int j = 0; j < 4; j++) acc[i][j] = 0.f;

    const float* Pbase = S + (size_t)bh * T_ * T_;
    const float* vbase = qkv + (size_t)(b * T_) * MQKV + 2 * D_ + h * HD_;

    for (int jt = 0; jt <= ti; jt++) {
        for (int idx = tid; idx < 64 * 16; idx += 256) {
            int r  = idx >> 4;
            int c4 = (idx & 15) * 4;
            float4 pv = *(const float4*)(Pbase + (size_t)(ti * 64 + r) * T_ + jt * 64 + c4);
            Ps[c4 + 0][r] = pv.x; Ps[c4 + 1][r] = pv.y;
            Ps[c4 + 2][r] = pv.z; Ps[c4 + 3][r] = pv.w;
            float4 vv = *(const float4*)(vbase + (size_t)(jt * 64 + r) * MQKV + c4);
            *(float4*)&Vs[r][c4] = vv;
        }
        __syncthreads();

#pragma unroll 16
        for (int j = 0; j < 64; j++) {
            float a[4], bb[4];
#pragma unroll
            for (int i = 0; i < 4; i++) a[i]  = Ps[j][ty * 4 + i];
#pragma unroll
            for (int e = 0; e < 4; e++) bb[e] = Vs[j][tx * 4 + e];
#pragma unroll
            for (int i = 0; i < 4; i++)
#pragma unroll
                for (int e = 0; e < 4; e++) acc[i][e] = fmaf(a[i], bb[e], acc[i][e]);
        }
        __syncthreads();
    }

#pragma unroll
    for (int i = 0; i < 4; i++) {
        int gi = ti * 64 + ty * 4 + i;
        float* crow = ctx + (size_t)(b * T_ + gi) * D_ + h * HD_ + tx * 4;
        float4 v = make_float4(acc[i][0], acc[i][1], acc[i][2], acc[i][3]);
        *(float4*)crow = v;
    }
}

// ---------------------------------------------------------------------------
extern "C" void kernel_launch(void* const* d_in, const int* in_sizes, int n_in,
                              void* d_out, int out_size)
{
    const float* x     = (const float*)d_in[0];
    const float* w_qkv = (const float*)d_in[1];
    const float* w_out = (const float*)d_in[2];
    float* out = (float*)d_out;

    float *qkv_p, *S_p, *ctx_p;
    cudaGetSymbolAddress((void**)&qkv_p, g_qkv);
    cudaGetSymbolAddress((void**)&S_p,   g_S);
    cudaGetSymbolAddress((void**)&ctx_p, g_ctx);

    __nv_bfloat16 *xhi, *xlo, *wqhi, *wqlo, *wohi, *wolo, *chi, *clo;
    cudaGetSymbolAddress((void**)&xhi,  g_xhi);
    cudaGetSymbolAddress((void**)&xlo,  g_xlo);
    cudaGetSymbolAddress((void**)&wqhi, g_wqhi);
    cudaGetSymbolAddress((void**)&wqlo, g_wqlo);
    cudaGetSymbolAddress((void**)&wohi, g_wohi);
    cudaGetSymbolAddress((void**)&wolo, g_wolo);
    cudaGetSymbolAddress((void**)&chi,  g_chi);
    cudaGetSymbolAddress((void**)&clo,  g_clo);

    // 0) bf16 hi/lo splits of x, w_qkv, w_out
    {
        int n4 = NTOK * K_ / 4;
        split_bf16<<<(n4 + 255) / 256, 256>>>(x, xhi, xlo, n4);
        n4 = MQKV * K_ / 4;
        split_bf16<<<(n4 + 255) / 256, 256>>>(w_qkv, wqhi, wqlo, n4);
        n4 = D_ * K_ / 4;
        split_bf16<<<(n4 + 255) / 256, 256>>>(w_out, wohi, wolo, n4);
    }

    // 1) QKV projection (tensor cores, bf16x3): [4096,1024] @ [3072,1024]^T
    gemm_bf16x3<<<dim3(MQKV / BN, NTOK / BM), 256>>>(xhi, xlo, wqhi, wqlo, qkv_p, MQKV);

    // 2) Scores (causal tiles only) + scale + ALiBi
    scores_kernel<<<dim3(T_ / 64, T_ / 64, B_ * H_), 256>>>(qkv_p, S_p);

    // 3) Row softmax (in place) with zero-padding of the diagonal tile
    softmax_kernel<<<dim3(T_, B_ * H_), 128>>>(S_p);

    // 4) P @ V -> ctx in [B,T,D] layout
    av_kernel<<<dim3(T_ / 64, B_ * H_), 256>>>(S_p, qkv_p, ctx_p);

    // 5) Output projection (tensor cores, bf16x3)
    {
        int n4 = NTOK * K_ / 4;
        split_bf16<<<(n4 + 255) / 256, 256>>>(ctx_p, chi, clo, n4);
    }
    gemm_bf16x3<<<dim3(D_ / BN, NTOK / BM), 256>>>(chi, clo, wohi, wolo, out, D_);
}

// round 9
// speedup vs baseline: 2.2417x; 1.6203x over previous
#include <cuda_runtime.h>
#include <cuda_bf16.h>
#include <math_constants.h>

// Fixed problem shapes
#define B_ 2
#define T_ 2048
#define D_ 1024
#define H_ 16
#define HD_ 64
#define NTOK (B_ * T_)          // 4096
#define MQKV (3 * D_)           // 3072
#define K_ 1024

// Scratch (allocation-free rule: __device__ globals)
__device__ float g_qkv[NTOK * MQKV];                       // [4096, 3072] fp32 q|k|v

// bf16 hi/lo split scratch
__device__ __nv_bfloat16 g_xhi[NTOK * K_],  g_xlo[NTOK * K_];
__device__ __nv_bfloat16 g_wqhi[MQKV * K_], g_wqlo[MQKV * K_];
__device__ __nv_bfloat16 g_wohi[D_ * K_],   g_wolo[D_ * K_];
__device__ __nv_bfloat16 g_chi[NTOK * K_],  g_clo[NTOK * K_];   // ctx hi/lo (flash output)

// ---------------------------------------------------------------------------
// helpers
// ---------------------------------------------------------------------------
__device__ __forceinline__ void split2(float x, float y, unsigned &hi, unsigned &lo)
{
    __nv_bfloat16 hx = __float2bfloat16(x), hy = __float2bfloat16(y);
    __nv_bfloat162 h(hx, hy);
    __nv_bfloat162 l(__float2bfloat16(x - __bfloat162float(hx)),
                     __float2bfloat16(y - __bfloat162float(hy)));
    hi = *(unsigned*)&h;
    lo = *(unsigned*)&l;
}

__device__ __forceinline__ void mma16816(float c[4], const unsigned a[4], const unsigned b[2])
{
    asm volatile(
        "mma.sync.aligned.m16n8k16.row.col.f32.bf16.bf16.f32 "
        "{%0,%1,%2,%3}, {%4,%5,%6,%7}, {%8,%9}, {%0,%1,%2,%3};\n"
        : "+f"(c[0]), "+f"(c[1]), "+f"(c[2]), "+f"(c[3])
        : "r"(a[0]), "r"(a[1]), "r"(a[2]), "r"(a[3]), "r"(b[0]), "r"(b[1]));
}

// ---------------------------------------------------------------------------
// Split fp32 -> bf16 hi + bf16 lo (residual). Vectorized by 4.
// ---------------------------------------------------------------------------
__global__ __launch_bounds__(256) void split_bf16(
    const float* __restrict__ in, __nv_bfloat16* __restrict__ hi,
    __nv_bfloat16* __restrict__ lo, int n4)
{
    int i = blockIdx.x * 256 + threadIdx.x;
    if (i >= n4) return;
    float4 v = ((const float4*)in)[i];
    unsigned h0, l0, h1, l1;
    split2(v.x, v.y, h0, l0);
    split2(v.z, v.w, h1, l1);
    ((unsigned*)hi)[i * 2 + 0] = h0;
    ((unsigned*)hi)[i * 2 + 1] = h1;
    ((unsigned*)lo)[i * 2 + 0] = l0;
    ((unsigned*)lo)[i * 2 + 1] = l1;
}

// ---------------------------------------------------------------------------
// Tensor-core NT GEMM, bf16x3 split: C[N,M] = A[N,K] @ W[M,K]^T in ~fp32 prec.
// mma.sync.m16n8k16.bf16. Block 128x128, BK=32, 8 warps, warp tile 64x32.
// ---------------------------------------------------------------------------
#define BM 128
#define BN 128
#define BK 32
#define SSTR 40

__global__ __launch_bounds__(256) void gemm_bf16x3(
    const __nv_bfloat16* __restrict__ Ahi, const __nv_bfloat16* __restrict__ Alo,
    const __nv_bfloat16* __restrict__ Whi, const __nv_bfloat16* __restrict__ Wlo,
    float* __restrict__ C, int Mcols)
{
    __shared__ __nv_bfloat16 sAhi[BM][SSTR], sAlo[BM][SSTR];
    __shared__ __nv_bfloat16 sBhi[BN][SSTR], sBlo[BN][SSTR];

    const int tid  = threadIdx.x;
    const int warp = tid >> 5;
    const int lane = tid & 31;
    const int wm = warp >> 2;
    const int wn = warp & 3;
    const int g  = lane >> 2;
    const int tg = lane & 3;
    const int rowBase = blockIdx.y * BM;
    const int colBase = blockIdx.x * BN;

    float acc[4][4][4];
#pragma unroll
    for (int im = 0; im < 4; im++)
#pragma unroll
        for (int in = 0; in < 4; in++)
#pragma unroll
            for (int q = 0; q < 4; q++) acc[im][in][q] = 0.f;

    uint4 pAh[2], pAl[2], pBh[2], pBl[2];

#pragma unroll
    for (int l = 0; l < 2; l++) {
        int idx = l * 256 + tid;
        int r = idx >> 2, c8 = (idx & 3) * 8;
        pAh[l] = *(const uint4*)(Ahi + (size_t)(rowBase + r) * K_ + c8);
        pAl[l] = *(const uint4*)(Alo + (size_t)(rowBase + r) * K_ + c8);
        pBh[l] = *(const uint4*)(Whi + (size_t)(colBase + r) * K_ + c8);
        pBl[l] = *(const uint4*)(Wlo + (size_t)(colBase + r) * K_ + c8);
    }

    for (int k0 = 0; k0 < K_; k0 += BK) {
#pragma unroll
        for (int l = 0; l < 2; l++) {
            int idx = l * 256 + tid;
            int r = idx >> 2, c8 = (idx & 3) * 8;
            *(uint4*)&sAhi[r][c8] = pAh[l];
            *(uint4*)&sAlo[r][c8] = pAl[l];
            *(uint4*)&sBhi[r][c8] = pBh[l];
            *(uint4*)&sBlo[r][c8] = pBl[l];
        }
        __syncthreads();

        if (k0 + BK < K_) {
#pragma unroll
            for (int l = 0; l < 2; l++) {
                int idx = l * 256 + tid;
                int r = idx >> 2, c8 = (idx & 3) * 8;
                pAh[l] = *(const uint4*)(Ahi + (size_t)(rowBase + r) * K_ + k0 + BK + c8);
                pAl[l] = *(const uint4*)(Alo + (size_t)(rowBase + r) * K_ + k0 + BK + c8);
                pBh[l] = *(const uint4*)(Whi + (size_t)(colBase + r) * K_ + k0 + BK + c8);
                pBl[l] = *(const uint4*)(Wlo + (size_t)(colBase + r) * K_ + k0 + BK + c8);
            }
        }

#pragma unroll
        for (int ks = 0; ks < BK; ks += 16) {
            unsigned ahi[4][4], alo[4][4], bhi[4][2], blo[4][2];
            const int c0 = ks + tg * 2;
#pragma unroll
            for (int im = 0; im < 4; im++) {
                int ra = wm * 64 + im * 16 + g;
                ahi[im][0] = *(const unsigned*)&sAhi[ra][c0];
                ahi[im][1] = *(const unsigned*)&sAhi[ra + 8][c0];
                ahi[im][2] = *(const unsigned*)&sAhi[ra][c0 + 8];
                ahi[im][3] = *(const unsigned*)&sAhi[ra + 8][c0 + 8];
                alo[im][0] = *(const unsigned*)&sAlo[ra][c0];
                alo[im][1] = *(const unsigned*)&sAlo[ra + 8][c0];
                alo[im][2] = *(const unsigned*)&sAlo[ra][c0 + 8];
                alo[im][3] = *(const unsigned*)&sAlo[ra + 8][c0 + 8];
            }
#pragma unroll
            for (int in = 0; in < 4; in++) {
                int nb = wn * 32 + in * 8 + g;
                bhi[in][0] = *(const unsigned*)&sBhi[nb][c0];
                bhi[in][1] = *(const unsigned*)&sBhi[nb][c0 + 8];
                blo[in][0] = *(const unsigned*)&sBlo[nb][c0];
                blo[in][1] = *(const unsigned*)&sBlo[nb][c0 + 8];
            }
#pragma unroll
            for (int im = 0; im < 4; im++)
#pragma unroll
                for (int in = 0; in < 4; in++) {
                    mma16816(acc[im][in], ahi[im], bhi[in]);
                    mma16816(acc[im][in], ahi[im], blo[in]);
                    mma16816(acc[im][in], alo[im], bhi[in]);
                }
        }
        __syncthreads();
    }

#pragma unroll
    for (int im = 0; im < 4; im++) {
#pragma unroll
        for (int in = 0; in < 4; in++) {
            int row = rowBase + wm * 64 + im * 16 + g;
            int col = colBase + wn * 32 + in * 8 + tg * 2;
            float2 v01 = make_float2(acc[im][in][0], acc[im][in][1]);
            float2 v23 = make_float2(acc[im][in][2], acc[im][in][3]);
            *(float2*)(C + (size_t)row * Mcols + col)       = v01;
            *(float2*)(C + (size_t)(row + 8) * Mcols + col) = v23;
        }
    }
}

// ---------------------------------------------------------------------------
// Fused flash attention: scores (scale+ALiBi+causal) + online softmax + P@V.
// Block = 128 q-rows (8 warps x 16 rows, per-warp softmax state), j-tiles of 64.
// QK^T and P@V via mma.m16n8k16.bf16 with hi/lo x3 split for ~fp32 precision.
// Writes ctx directly as bf16 hi/lo for the output projection.
// ---------------------------------------------------------------------------
#define FSTR 72   // smem row stride (bf16), conflict-free fragment loads

__global__ __launch_bounds__(256, 1) void flash_kernel(
    const float* __restrict__ qkv,
    __nv_bfloat16* __restrict__ chi, __nv_bfloat16* __restrict__ clo)
{
    __shared__ __nv_bfloat16 sKhi[64][FSTR], sKlo[64][FSTR];
    __shared__ __nv_bfloat16 sVhi[64][FSTR], sVlo[64][FSTR];   // transposed: [e][j]

    const int iblk = (int)gridDim.x - 1 - (int)blockIdx.x;  // big tiles first
    const int bh   = blockIdx.y;
    const int b    = bh >> 4;
    const int h    = bh & 15;
    const int tid  = threadIdx.x;
    const int warp = tid >> 5;
    const int lane = tid & 31;
    const int g    = lane >> 2;
    const int tg   = lane & 3;
    const int rbase = iblk * 128 + warp * 16;               // batch-local q-row base of warp
    const float slope = exp2f(-(float)(h + 1) / 16.f);

    const float* qkbase = qkv + (size_t)(b * T_) * MQKV + h * HD_;

    // Q fragments straight from gmem fp32 (once per block), hi/lo split
    unsigned qhi[4][4], qlo[4][4];
#pragma unroll
    for (int kb = 0; kb < 4; kb++)
#pragma unroll
        for (int r = 0; r < 4; r++) {
            int row = rbase + g + (r & 1) * 8;
            int col = kb * 16 + tg * 2 + (r >> 1) * 8;
            float2 v = *(const float2*)(qkbase + (size_t)row * MQKV + col);
            split2(v.x, v.y, qhi[kb][r], qlo[kb][r]);
        }

    float acc_o[8][4];
#pragma unroll
    for (int nf = 0; nf < 8; nf++)
#pragma unroll
        for (int q = 0; q < 4; q++) acc_o[nf][q] = 0.f;
    float m0 = -CUDART_INF_F, m1 = -CUDART_INF_F;
    float l0 = 0.f, l1 = 0.f;

    const int gi0 = rbase + g;
    const int gi1 = gi0 + 8;
    const int jt_max = (iblk * 128 + 127) >> 6;

    // per-thread K/V load coords (hoisted out of the jt loop)
    const int ldj  = tid >> 4;              // 0..15 base row (stride 16 over 4 its)
    const int lde4 = (tid & 15) * 4;        // element-4 column

    for (int jt = 0; jt <= jt_max; jt++) {
        // load K (row layout) and V (transposed) tiles, fp32 -> bf16 hi/lo
        const float* tilebase = qkbase + (size_t)(jt * 64) * MQKV;
#pragma unroll
        for (int it = 0; it < 4; it++) {
            int j = it * 16 + ldj;
            const float* src = tilebase + (size_t)j * MQKV;
            float4 kv = *(const float4*)(src + D_ + lde4);
            unsigned kh0, kl0, kh1, kl1;
            split2(kv.x, kv.y, kh0, kl0);
            split2(kv.z, kv.w, kh1, kl1);
            *(unsigned*)&sKhi[j][lde4]     = kh0;
            *(unsigned*)&sKhi[j][lde4 + 2] = kh1;
            *(unsigned*)&sKlo[j][lde4]     = kl0;
            *(unsigned*)&sKlo[j][lde4 + 2] = kl1;

            float4 vv = *(const float4*)(src + 2 * D_ + lde4);
            float vf[4] = {vv.x, vv.y, vv.z, vv.w};
#pragma unroll
            for (int q = 0; q < 4; q++) {
                __nv_bfloat16 hb = __float2bfloat16(vf[q]);
                sVhi[lde4 + q][j] = hb;
                sVlo[lde4 + q][j] = __float2bfloat16(vf[q] - __bfloat162float(hb));
            }
        }
        __syncthreads();

        if (jt * 64 <= rbase + 15) {
            // --- S = Q K^T (bf16x3) ---
            float s[8][4];
#pragma unroll
            for (int nf = 0; nf < 8; nf++)
#pragma unroll
                for (int q = 0; q < 4; q++) s[nf][q] = 0.f;

#pragma unroll
            for (int kb = 0; kb < 4; kb++) {
                const int c0 = kb * 16 + tg * 2;
#pragma unroll
                for (int nf = 0; nf < 8; nf++) {
                    unsigned kbh[2], kbl[2];
                    kbh[0] = *(const unsigned*)&sKhi[nf * 8 + g][c0];
                    kbh[1] = *(const unsigned*)&sKhi[nf * 8 + g][c0 + 8];
                    kbl[0] = *(const unsigned*)&sKlo[nf * 8 + g][c0];
                    kbl[1] = *(const unsigned*)&sKlo[nf * 8 + g][c0 + 8];
                    mma16816(s[nf], qhi[kb], kbh);
                    mma16816(s[nf], qlo[kb], kbh);
                    mma16816(s[nf], qhi[kb], kbl);
                }
            }

            // --- scale + ALiBi + causal mask ---
#pragma unroll
            for (int nf = 0; nf < 8; nf++) {
                int j0 = jt * 64 + nf * 8 + tg * 2;
                s[nf][0] = (j0     <= gi0) ? s[nf][0] * 0.125f + slope * (float)(j0     - gi0) : -CUDART_INF_F;
                s[nf][1] = (j0 + 1 <= gi0) ? s[nf][1] * 0.125f + slope * (float)(j0 + 1 - gi0) : -CUDART_INF_F;
                s[nf][2] = (j0     <= gi1) ? s[nf][2] * 0.125f + slope * (float)(j0     - gi1) : -CUDART_INF_F;
                s[nf][3] = (j0 + 1 <= gi1) ? s[nf][3] * 0.125f + slope * (float)(j0 + 1 - gi1) : -CUDART_INF_F;
            }

            // --- online softmax update ---
            float tm0 = -CUDART_INF_F, tm1 = -CUDART_INF_F;
#pragma unroll
            for (int nf = 0; nf < 8; nf++) {
                tm0 = fmaxf(tm0, fmaxf(s[nf][0], s[nf][1]));
                tm1 = fmaxf(tm1, fmaxf(s[nf][2], s[nf][3]));
            }
            tm0 = fmaxf(tm0, __shfl_xor_sync(0xffffffffu, tm0, 1));
            tm0 = fmaxf(tm0, __shfl_xor_sync(0xffffffffu, tm0, 2));
            tm1 = fmaxf(tm1, __shfl_xor_sync(0xffffffffu, tm1, 1));
            tm1 = fmaxf(tm1, __shfl_xor_sync(0xffffffffu, tm1, 2));
            float mn0 = fmaxf(m0, tm0), mn1 = fmaxf(m1, tm1);
            float a0 = __expf(m0 - mn0), a1 = __expf(m1 - mn1);

            float sum0 = 0.f, sum1 = 0.f;
#pragma unroll
            for (int nf = 0; nf < 8; nf++) {
                s[nf][0] = __expf(s[nf][0] - mn0);
                s[nf][1] = __expf(s[nf][1] - mn0);
                s[nf][2] = __expf(s[nf][2] - mn1);
                s[nf][3] = __expf(s[nf][3] - mn1);
                sum0 += s[nf][0] + s[nf][1];
                sum1 += s[nf][2] + s[nf][3];
            }
            sum0 += __shfl_xor_sync(0xffffffffu, sum0, 1);
            sum0 += __shfl_xor_sync(0xffffffffu, sum0, 2);
            sum1 += __shfl_xor_sync(0xffffffffu, sum1, 1);
            sum1 += __shfl_xor_sync(0xffffffffu, sum1, 2);
            l0 = l0 * a0 + sum0;
            l1 = l1 * a1 + sum1;
            m0 = mn0; m1 = mn1;

#pragma unroll
            for (int nf = 0; nf < 8; nf++) {
                acc_o[nf][0] *= a0; acc_o[nf][1] *= a0;
                acc_o[nf][2] *= a1; acc_o[nf][3] *= a1;
            }

            // --- O += P @ V : S-accum frags feed A operand directly ---
#pragma unroll
            for (int kb = 0; kb < 4; kb++) {
                unsigned pah[4], pal[4];
                split2(s[2 * kb][0],     s[2 * kb][1],     pah[0], pal[0]);
                split2(s[2 * kb][2],     s[2 * kb][3],     pah[1], pal[1]);
                split2(s[2 * kb + 1][0], s[2 * kb + 1][1], pah[2], pal[2]);
                split2(s[2 * kb + 1][2], s[2 * kb + 1][3], pah[3], pal[3]);
                const int c0 = kb * 16 + tg * 2;
#pragma unroll
                for (int nf = 0; nf < 8; nf++) {
                    unsigned vbh[2], vbl[2];
                    vbh[0] = *(const unsigned*)&sVhi[nf * 8 + g][c0];
                    vbh[1] = *(const unsigned*)&sVhi[nf * 8 + g][c0 + 8];
                    vbl[0] = *(const unsigned*)&sVlo[nf * 8 + g][c0];
                    vbl[1] = *(const unsigned*)&sVlo[nf * 8 + g][c0 + 8];
                    mma16816(acc_o[nf], pah, vbh);
                    mma16816(acc_o[nf], pal, vbh);
                    mma16816(acc_o[nf], pah, vbl);
                }
            }
        }
        __syncthreads();
    }

    // --- epilogue: O /= l, write ctx as bf16 hi/lo ---
    const float r0 = 1.f / l0, r1 = 1.f / l1;
    const size_t base0 = (size_t)(b * T_ + gi0) * D_ + h * HD_;
    const size_t base1 = base0 + (size_t)8 * D_;
#pragma unroll
    for (int nf = 0; nf < 8; nf++) {
        int col = nf * 8 + tg * 2;
        unsigned uh, ul;
        split2(acc_o[nf][0] * r0, acc_o[nf][1] * r0, uh, ul);
        *(unsigned*)(chi + base0 + col) = uh;
        *(unsigned*)(clo + base0 + col) = ul;
        split2(acc_o[nf][2] * r1, acc_o[nf][3] * r1, uh, ul);
        *(unsigned*)(chi + base1 + col) = uh;
        *(unsigned*)(clo + base1 + col) = ul;
    }
}

// ---------------------------------------------------------------------------
extern "C" void kernel_launch(void* const* d_in, const int* in_sizes, int n_in,
                              void* d_out, int out_size)
{
    const float* x     = (const float*)d_in[0];
    const float* w_qkv = (const float*)d_in[1];
    const float* w_out = (const float*)d_in[2];
    float* out = (float*)d_out;

    float* qkv_p;
    cudaGetSymbolAddress((void**)&qkv_p, g_qkv);

    __nv_bfloat16 *xhi, *xlo, *wqhi, *wqlo, *wohi, *wolo, *chi, *clo;
    cudaGetSymbolAddress((void**)&xhi,  g_xhi);
    cudaGetSymbolAddress((void**)&xlo,  g_xlo);
    cudaGetSymbolAddress((void**)&wqhi, g_wqhi);
    cudaGetSymbolAddress((void**)&wqlo, g_wqlo);
    cudaGetSymbolAddress((void**)&wohi, g_wohi);
    cudaGetSymbolAddress((void**)&wolo, g_wolo);
    cudaGetSymbolAddress((void**)&chi,  g_chi);
    cudaGetSymbolAddress((void**)&clo,  g_clo);

    // 0) bf16 hi/lo splits of x, w_qkv, w_out
    {
        int n4 = NTOK * K_ / 4;
        split_bf16<<<(n4 + 255) / 256, 256>>>(x, xhi, xlo, n4);
        n4 = MQKV * K_ / 4;
        split_bf16<<<(n4 + 255) / 256, 256>>>(w_qkv, wqhi, wqlo, n4);
        n4 = D_ * K_ / 4;
        split_bf16<<<(n4 + 255) / 256, 256>>>(w_out, wohi, wolo, n4);
    }

    // 1) QKV projection (tensor cores, bf16x3): [4096,1024] @ [3072,1024]^T
    gemm_bf16x3<<<dim3(MQKV / BN, NTOK / BM), 256>>>(xhi, xlo, wqhi, wqlo, qkv_p, MQKV);

    // 2) Fused flash attention (scores + ALiBi + causal softmax + P@V),
    //    writes ctx directly as bf16 hi/lo
    flash_kernel<<<dim3(T_ / 128, B_ * H_), 256>>>(qkv_p, chi, clo);

    // 3) Output projection (tensor cores, bf16x3)
    gemm_bf16x3<<<dim3(D_ / BN, NTOK / BM), 256>>>(chi, clo, wohi, wolo, out, D_);
}